// round 1
// baseline (speedup 1.0000x reference)
#include <cuda_runtime.h>
#include <math_constants.h>

#define BB 2
#define LL 2048
#define DM 256
#define NH 8
#define DEPTH 32
#define QT 64
#define KT 32
#define NEG_INF_F (-4294967296.0f)   /* float32(-2^32+1) */

// Scratch (allocation-free rule: __device__ globals)
__device__ float g_Q[BB*LL*DM];
__device__ float g_K[BB*LL*DM];
__device__ float g_V[BB*LL*DM];
__device__ float g_AO[BB*LL*DM];

// ---------------------------------------------------------------------------
// GEMM: C[M,256] = A[M,256] @ W[256,256] + bias   (M = 4096)
// 64x64 tile, BK=32, 256 threads, 4x4 microtile
// ---------------------------------------------------------------------------
__global__ __launch_bounds__(256) void gemm_bias_kernel(
    const float* __restrict__ A, const float* __restrict__ W,
    const float* __restrict__ bias, float* __restrict__ C)
{
    __shared__ float As[64][33];
    __shared__ float Ws[32][64];

    const int tx = threadIdx.x & 15;
    const int ty = threadIdx.x >> 4;
    const int m0 = blockIdx.x * 64;
    const int n0 = blockIdx.y * 64;

    float acc[4][4] = {};

    for (int kt = 0; kt < 256; kt += 32) {
        // A tile 64x32 (coalesced over k)
        {
            const int k = threadIdx.x & 31;
            const int m = threadIdx.x >> 5;      // 0..7
            #pragma unroll
            for (int p = 0; p < 8; p++)
                As[m + p*8][k] = A[(size_t)(m0 + m + p*8)*256 + kt + k];
        }
        // W tile 32x64 (coalesced over n)
        {
            const int n = threadIdx.x & 63;
            const int k = threadIdx.x >> 6;      // 0..3
            #pragma unroll
            for (int p = 0; p < 8; p++)
                Ws[k + p*4][n] = W[(size_t)(kt + k + p*4)*256 + n0 + n];
        }
        __syncthreads();

        #pragma unroll
        for (int k = 0; k < 32; k++) {
            float a[4];
            #pragma unroll
            for (int i = 0; i < 4; i++) a[i] = As[ty*4 + i][k];
            float4 wv = reinterpret_cast<const float4*>(&Ws[k][0])[tx];
            #pragma unroll
            for (int i = 0; i < 4; i++) {
                acc[i][0] += a[i]*wv.x; acc[i][1] += a[i]*wv.y;
                acc[i][2] += a[i]*wv.z; acc[i][3] += a[i]*wv.w;
            }
        }
        __syncthreads();
    }

    #pragma unroll
    for (int i = 0; i < 4; i++) {
        const int m = m0 + ty*4 + i;
        #pragma unroll
        for (int j = 0; j < 4; j++) {
            const int n = n0 + tx*4 + j;
            C[(size_t)m*256 + n] = acc[i][j] + bias[n];
        }
    }
}

// ---------------------------------------------------------------------------
// Flash-style attention, one head-slice per CTA.
// Block: 128 threads = 2 key-groups x 64 queries. Each thread owns one query,
// processes half the keys (32 tiles of 32 keys) with online softmax, then the
// two halves are merged through shared memory.
// ---------------------------------------------------------------------------
__global__ __launch_bounds__(128) void attn_kernel(
    const int* __restrict__ key_mask, float* __restrict__ AO)
{
    __shared__ float Ks[2][KT][DEPTH];   // 8 KB
    __shared__ float Vs[2][KT][DEPTH];   // 8 KB
    __shared__ int   Ms[2][KT];

    const int b  = blockIdx.z;
    const int h  = blockIdx.y;
    const int t  = threadIdx.x;
    const int g  = t >> 6;               // key group 0/1
    const int ql = t & 63;
    const int q  = blockIdx.x * QT + ql;

    // load this thread's query row into registers
    const float* Qp = g_Q + ((size_t)(b*LL + q))*DM + h*DEPTH;
    float qreg[DEPTH];
    #pragma unroll
    for (int d4 = 0; d4 < 8; d4++) {
        float4 v = reinterpret_cast<const float4*>(Qp)[d4];
        qreg[d4*4+0]=v.x; qreg[d4*4+1]=v.y; qreg[d4*4+2]=v.z; qreg[d4*4+3]=v.w;
    }

    float m = -CUDART_INF_F, l = 0.f;
    float o[DEPTH];
    #pragma unroll
    for (int d = 0; d < DEPTH; d++) o[d] = 0.f;

    const float scale = 0.17677669529663687f;  // 1/sqrt(32)

    for (int it = 0; it < 32; it++) {
        // Cooperative load of two 32x32 K and V tiles (float4)
        #pragma unroll
        for (int i = 0; i < 4; i++) {
            const int f    = t + i*128;      // float4 index 0..511
            const int slot = f >> 8;
            const int r    = (f >> 3) & 31;
            const int d4   = f & 7;
            const int k    = (slot*32 + it)*KT + r;
            const size_t ga = ((size_t)(b*LL + k))*DM + h*DEPTH;
            reinterpret_cast<float4*>(Ks[slot][r])[d4] =
                reinterpret_cast<const float4*>(g_K + ga)[d4];
            reinterpret_cast<float4*>(Vs[slot][r])[d4] =
                reinterpret_cast<const float4*>(g_V + ga)[d4];
        }
        if (t < 64) {
            const int slot = t >> 5, r = t & 31;
            Ms[slot][r] = key_mask[b*LL + (slot*32 + it)*KT + r];
        }
        __syncthreads();

        // scores for 32 keys
        float sj[KT];
        float tmax = -CUDART_INF_F;
        #pragma unroll
        for (int j = 0; j < KT; j++) {
            float s = 0.f;
            #pragma unroll
            for (int d4 = 0; d4 < 8; d4++) {
                float4 kv = reinterpret_cast<const float4*>(Ks[g][j])[d4];
                s += qreg[d4*4+0]*kv.x + qreg[d4*4+1]*kv.y
                   + qreg[d4*4+2]*kv.z + qreg[d4*4+3]*kv.w;
            }
            s *= scale;
            if (Ms[g][j] == 0) s = NEG_INF_F;
            sj[j] = s;
            tmax = fmaxf(tmax, s);
        }

        const float mn    = fmaxf(m, tmax);
        const float alpha = __expf(m - mn);
        l *= alpha;
        #pragma unroll
        for (int d = 0; d < DEPTH; d++) o[d] *= alpha;

        #pragma unroll
        for (int j = 0; j < KT; j++) {
            const float p = __expf(sj[j] - mn);
            l += p;
            #pragma unroll
            for (int d4 = 0; d4 < 8; d4++) {
                float4 vv = reinterpret_cast<const float4*>(Vs[g][j])[d4];
                o[d4*4+0] += p*vv.x; o[d4*4+1] += p*vv.y;
                o[d4*4+2] += p*vv.z; o[d4*4+3] += p*vv.w;
            }
        }
        m = mn;
        __syncthreads();
    }

    // merge group 1 state into group 0 via smem (reuse Ks/Vs)
    float* mlbuf = &Ks[0][0][0];        // 128 floats: [ql*2]=m, [ql*2+1]=l
    float* obuf  = &Vs[0][0][0];        // 64*32 floats

    if (g == 1) {
        mlbuf[ql*2]     = m;
        mlbuf[ql*2 + 1] = l;
        #pragma unroll
        for (int d = 0; d < DEPTH; d++) obuf[ql*DEPTH + d] = o[d];
    }
    __syncthreads();

    if (g == 0) {
        const float m2 = mlbuf[ql*2];
        const float l2 = mlbuf[ql*2 + 1];
        const float M  = fmaxf(m, m2);
        const float a1 = __expf(m  - M);
        const float a2 = __expf(m2 - M);
        const float inv = 1.f / (l*a1 + l2*a2);

        float* outp = AO + ((size_t)(b*LL + q))*DM + h*DEPTH;
        #pragma unroll
        for (int d4 = 0; d4 < 8; d4++) {
            float4 r;
            r.x = (o[d4*4+0]*a1 + obuf[ql*DEPTH + d4*4+0]*a2) * inv;
            r.y = (o[d4*4+1]*a1 + obuf[ql*DEPTH + d4*4+1]*a2) * inv;
            r.z = (o[d4*4+2]*a1 + obuf[ql*DEPTH + d4*4+2]*a2) * inv;
            r.w = (o[d4*4+3]*a1 + obuf[ql*DEPTH + d4*4+3]*a2) * inv;
            reinterpret_cast<float4*>(outp)[d4] = r;
        }
    }
}

// ---------------------------------------------------------------------------
extern "C" void kernel_launch(void* const* d_in, const int* in_sizes, int n_in,
                              void* d_out, int out_size)
{
    const float* queries  = (const float*)d_in[0];
    const float* keys     = (const float*)d_in[1];
    const float* values   = (const float*)d_in[2];
    const int*   key_mask = (const int*)  d_in[3];
    const float* Wq = (const float*)d_in[4];  const float* bq = (const float*)d_in[5];
    const float* Wk = (const float*)d_in[6];  const float* bk = (const float*)d_in[7];
    const float* Wv = (const float*)d_in[8];  const float* bv = (const float*)d_in[9];
    const float* Wo = (const float*)d_in[10]; const float* bo = (const float*)d_in[11];
    float* out = (float*)d_out;

    float *Qd, *Kd, *Vd, *AOd;
    cudaGetSymbolAddress((void**)&Qd,  g_Q);
    cudaGetSymbolAddress((void**)&Kd,  g_K);
    cudaGetSymbolAddress((void**)&Vd,  g_V);
    cudaGetSymbolAddress((void**)&AOd, g_AO);

    const dim3 ggrid(64, 4);   // M/64 x N/64, M = B*L = 4096, N = 256
    gemm_bias_kernel<<<ggrid, 256>>>(queries, Wq, bq, Qd);
    gemm_bias_kernel<<<ggrid, 256>>>(keys,    Wk, bk, Kd);
    gemm_bias_kernel<<<ggrid, 256>>>(values,  Wv, bv, Vd);

    const dim3 agrid(LL/QT, NH, BB);   // 32 x 8 x 2 = 512 CTAs
    attn_kernel<<<agrid, 128>>>(key_mask, AOd);

    gemm_bias_kernel<<<ggrid, 256>>>(AOd, Wo, bo, out);
}

// round 2
// speedup vs baseline: 2.2014x; 2.2014x over previous
#include <cuda_runtime.h>
#include <math_constants.h>

#define BB 2
#define LL 2048
#define DM 256
#define NH 8
#define DEPTH 32
#define KT 64
#define NEG_INF_F (-4294967296.0f)   /* float32(-2^32+1) */

// Scratch (allocation-free rule: __device__ globals)
__device__ float g_Q[BB*LL*DM];
__device__ float g_K[BB*LL*DM];
__device__ float g_V[BB*LL*DM];
__device__ float g_AO[BB*LL*DM];

__device__ __forceinline__ unsigned f2tf(float x) {
    unsigned r;
    asm("cvt.rna.tf32.f32 %0, %1;" : "=r"(r) : "f"(x));
    return r;
}

__device__ __forceinline__ void mma_tf32(float d[4], const unsigned a[4],
                                         const unsigned b[2], const float c[4]) {
    asm volatile("mma.sync.aligned.m16n8k8.row.col.f32.tf32.tf32.f32 "
                 "{%0,%1,%2,%3}, {%4,%5,%6,%7}, {%8,%9}, {%10,%11,%12,%13};"
                 : "=f"(d[0]), "=f"(d[1]), "=f"(d[2]), "=f"(d[3])
                 : "r"(a[0]), "r"(a[1]), "r"(a[2]), "r"(a[3]),
                   "r"(b[0]), "r"(b[1]),
                   "f"(c[0]), "f"(c[1]), "f"(c[2]), "f"(c[3]));
}

// ---------------------------------------------------------------------------
// GEMM: C[M,256] = A[M,256] @ W[256,256] + bias   (M = 4096)  (fp32 SIMT)
// ---------------------------------------------------------------------------
__global__ __launch_bounds__(256) void gemm_bias_kernel(
    const float* __restrict__ A, const float* __restrict__ W,
    const float* __restrict__ bias, float* __restrict__ C)
{
    __shared__ float As[64][33];
    __shared__ float Ws[32][64];

    const int tx = threadIdx.x & 15;
    const int ty = threadIdx.x >> 4;
    const int m0 = blockIdx.x * 64;
    const int n0 = blockIdx.y * 64;

    float acc[4][4] = {};

    for (int kt = 0; kt < 256; kt += 32) {
        {
            const int k = threadIdx.x & 31;
            const int m = threadIdx.x >> 5;
            #pragma unroll
            for (int p = 0; p < 8; p++)
                As[m + p*8][k] = A[(size_t)(m0 + m + p*8)*256 + kt + k];
        }
        {
            const int n = threadIdx.x & 63;
            const int k = threadIdx.x >> 6;
            #pragma unroll
            for (int p = 0; p < 8; p++)
                Ws[k + p*4][n] = W[(size_t)(kt + k + p*4)*256 + n0 + n];
        }
        __syncthreads();

        #pragma unroll
        for (int k = 0; k < 32; k++) {
            float a[4];
            #pragma unroll
            for (int i = 0; i < 4; i++) a[i] = As[ty*4 + i][k];
            float4 wv = reinterpret_cast<const float4*>(&Ws[k][0])[tx];
            #pragma unroll
            for (int i = 0; i < 4; i++) {
                acc[i][0] += a[i]*wv.x; acc[i][1] += a[i]*wv.y;
                acc[i][2] += a[i]*wv.z; acc[i][3] += a[i]*wv.w;
            }
        }
        __syncthreads();
    }

    #pragma unroll
    for (int i = 0; i < 4; i++) {
        const int m = m0 + ty*4 + i;
        #pragma unroll
        for (int j = 0; j < 4; j++) {
            const int n = n0 + tx*4 + j;
            C[(size_t)m*256 + n] = acc[i][j] + bias[n];
        }
    }
}

// ---------------------------------------------------------------------------
// FA2-style attention with mma.sync tf32.
// CTA: 128 threads = 4 warps, each warp owns 16 queries (CTA: 64 queries).
// Key tiles of 64 in smem. QK^T via 3x-split tf32 (fp32-grade scores);
// PV via plain tf32. Mask folded into accumulator init.
// ---------------------------------------------------------------------------
__global__ __launch_bounds__(128) void attn_kernel(
    const int* __restrict__ key_mask, float* __restrict__ AO)
{
    __shared__ float    Qs[64][36];      // pad 36: stride ≡ 4 (mod 32)
    __shared__ unsigned Kh[64][36];      // K hi, tf32 bits
    __shared__ unsigned Kl[64][36];      // K lo, tf32 bits
    __shared__ unsigned Vs[64][40];      // V, tf32 bits; pad 40: stride ≡ 8 (mod 32)
    __shared__ float    biasS[64];       // mask bias per key

    const int b    = blockIdx.z;
    const int h    = blockIdx.y;
    const int t    = threadIdx.x;
    const int w    = t >> 5;
    const int lane = t & 31;
    const int g    = lane >> 2;          // group id (row)
    const int c    = lane & 3;           // thread in group (col quad)
    const int q0   = blockIdx.x * 64;

    const float scale = 0.17677669529663687f;  // 1/sqrt(32)

    // ---- stage Q tile (64x32) into smem ----
    const float* Qg = g_Q + ((size_t)(b*LL + q0))*DM + h*DEPTH;
    #pragma unroll
    for (int i = 0; i < 4; i++) {
        const int f = t + i*128;         // 0..511 float4s
        const int r = f >> 3, d4 = f & 7;
        reinterpret_cast<float4*>(&Qs[r][0])[d4] =
            reinterpret_cast<const float4*>(Qg + (size_t)r*DM)[d4];
    }
    __syncthreads();

    // ---- per-warp Q A-fragments (scaled, hi/lo split) ----
    unsigned qh[4][4], ql[4][4];
    {
        const int r0 = w*16 + g, r1 = r0 + 8;
        #pragma unroll
        for (int kc = 0; kc < 4; kc++) {
            const int c0 = kc*8 + c, c1 = c0 + 4;
            float v[4] = { Qs[r0][c0]*scale, Qs[r1][c0]*scale,
                           Qs[r0][c1]*scale, Qs[r1][c1]*scale };
            #pragma unroll
            for (int j = 0; j < 4; j++) {
                unsigned hi = f2tf(v[j]);
                qh[kc][j] = hi;
                ql[kc][j] = f2tf(v[j] - __uint_as_float(hi));
            }
        }
    }

    float o[4][4];
    #pragma unroll
    for (int i = 0; i < 4; i++)
        #pragma unroll
        for (int j = 0; j < 4; j++) o[i][j] = 0.f;
    float m0 = -CUDART_INF_F, m1 = -CUDART_INF_F;
    float l0 = 0.f, l1 = 0.f;

    const int src0 = (lane & 28) | (c >> 1);
    const int src2 = src0 + 2;
    const bool odd = (c & 1);

    for (int it = 0; it < LL/KT; it++) {
        const int k0 = it * KT;
        __syncthreads();   // previous tile fully consumed

        // ---- stage K (hi/lo tf32) and V (tf32) tiles ----
        const float* Kg = g_K + ((size_t)(b*LL + k0))*DM + h*DEPTH;
        const float* Vg = g_V + ((size_t)(b*LL + k0))*DM + h*DEPTH;
        #pragma unroll
        for (int i = 0; i < 4; i++) {
            const int f = t + i*128;
            const int r = f >> 3, d4 = f & 7;
            float4 kv = reinterpret_cast<const float4*>(Kg + (size_t)r*DM)[d4];
            uint4 hh, llo;
            hh.x = f2tf(kv.x); llo.x = f2tf(kv.x - __uint_as_float(hh.x));
            hh.y = f2tf(kv.y); llo.y = f2tf(kv.y - __uint_as_float(hh.y));
            hh.z = f2tf(kv.z); llo.z = f2tf(kv.z - __uint_as_float(hh.z));
            hh.w = f2tf(kv.w); llo.w = f2tf(kv.w - __uint_as_float(hh.w));
            *reinterpret_cast<uint4*>(&Kh[r][d4*4]) = hh;
            *reinterpret_cast<uint4*>(&Kl[r][d4*4]) = llo;
            float4 vv = reinterpret_cast<const float4*>(Vg + (size_t)r*DM)[d4];
            uint4 vt;
            vt.x = f2tf(vv.x); vt.y = f2tf(vv.y);
            vt.z = f2tf(vv.z); vt.w = f2tf(vv.w);
            *reinterpret_cast<uint4*>(&Vs[r][d4*4]) = vt;
        }
        if (t < 64)
            biasS[t] = key_mask[b*LL + k0 + t] ? 0.f : NEG_INF_F;
        __syncthreads();

        // ---- scores S = Q K^T (+ mask bias), 16x64 per warp ----
        float p[8][4];
        #pragma unroll
        for (int nt = 0; nt < 8; nt++) {
            const float bc0 = biasS[nt*8 + 2*c];
            const float bc1 = biasS[nt*8 + 2*c + 1];
            p[nt][0] = bc0; p[nt][1] = bc1; p[nt][2] = bc0; p[nt][3] = bc1;
            #pragma unroll
            for (int kc = 0; kc < 4; kc++) {
                const int key = nt*8 + g;
                const int d0  = kc*8 + c;
                unsigned bh[2] = { Kh[key][d0], Kh[key][d0+4] };
                unsigned bl[2] = { Kl[key][d0], Kl[key][d0+4] };
                mma_tf32(p[nt], qh[kc], bh, p[nt]);
                mma_tf32(p[nt], qh[kc], bl, p[nt]);
                mma_tf32(p[nt], ql[kc], bh, p[nt]);
            }
        }

        // ---- online softmax update ----
        float rmax0 = -CUDART_INF_F, rmax1 = -CUDART_INF_F;
        #pragma unroll
        for (int nt = 0; nt < 8; nt++) {
            rmax0 = fmaxf(rmax0, fmaxf(p[nt][0], p[nt][1]));
            rmax1 = fmaxf(rmax1, fmaxf(p[nt][2], p[nt][3]));
        }
        rmax0 = fmaxf(rmax0, __shfl_xor_sync(0xffffffffu, rmax0, 1));
        rmax0 = fmaxf(rmax0, __shfl_xor_sync(0xffffffffu, rmax0, 2));
        rmax1 = fmaxf(rmax1, __shfl_xor_sync(0xffffffffu, rmax1, 1));
        rmax1 = fmaxf(rmax1, __shfl_xor_sync(0xffffffffu, rmax1, 2));

        const float mn0 = fmaxf(m0, rmax0);
        const float mn1 = fmaxf(m1, rmax1);
        const float al0 = __expf(m0 - mn0);
        const float al1 = __expf(m1 - mn1);
        m0 = mn0; m1 = mn1;
        l0 *= al0; l1 *= al1;
        #pragma unroll
        for (int dt = 0; dt < 4; dt++) {
            o[dt][0] *= al0; o[dt][1] *= al0;
            o[dt][2] *= al1; o[dt][3] *= al1;
        }

        float rs0 = 0.f, rs1 = 0.f;
        #pragma unroll
        for (int nt = 0; nt < 8; nt++) {
            p[nt][0] = __expf(p[nt][0] - mn0); rs0 += p[nt][0];
            p[nt][1] = __expf(p[nt][1] - mn0); rs0 += p[nt][1];
            p[nt][2] = __expf(p[nt][2] - mn1); rs1 += p[nt][2];
            p[nt][3] = __expf(p[nt][3] - mn1); rs1 += p[nt][3];
        }
        rs0 += __shfl_xor_sync(0xffffffffu, rs0, 1);
        rs0 += __shfl_xor_sync(0xffffffffu, rs0, 2);
        rs1 += __shfl_xor_sync(0xffffffffu, rs1, 1);
        rs1 += __shfl_xor_sync(0xffffffffu, rs1, 2);
        l0 += rs0; l1 += rs1;

        // ---- O += P V  (P C-frag -> A-frag via quad shuffles) ----
        #pragma unroll
        for (int kc = 0; kc < 8; kc++) {
            float e00 = __shfl_sync(0xffffffffu, p[kc][0], src0);
            float e01 = __shfl_sync(0xffffffffu, p[kc][1], src0);
            float e10 = __shfl_sync(0xffffffffu, p[kc][2], src0);
            float e11 = __shfl_sync(0xffffffffu, p[kc][3], src0);
            float f00 = __shfl_sync(0xffffffffu, p[kc][0], src2);
            float f01 = __shfl_sync(0xffffffffu, p[kc][1], src2);
            float f10 = __shfl_sync(0xffffffffu, p[kc][2], src2);
            float f11 = __shfl_sync(0xffffffffu, p[kc][3], src2);
            unsigned pa[4];
            pa[0] = f2tf(odd ? e01 : e00);
            pa[1] = f2tf(odd ? e11 : e10);
            pa[2] = f2tf(odd ? f01 : f00);
            pa[3] = f2tf(odd ? f11 : f10);
            #pragma unroll
            for (int dt = 0; dt < 4; dt++) {
                unsigned vb[2] = { Vs[kc*8 + c][dt*8 + g],
                                   Vs[kc*8 + c + 4][dt*8 + g] };
                mma_tf32(o[dt], pa, vb, o[dt]);
            }
        }
    }

    // ---- normalize + store ----
    const float inv0 = 1.f / l0;
    const float inv1 = 1.f / l1;
    const int row0 = q0 + w*16 + g;
    const int row1 = row0 + 8;
    #pragma unroll
    for (int dt = 0; dt < 4; dt++) {
        const int d = h*DEPTH + dt*8 + 2*c;
        float2 r0v = make_float2(o[dt][0]*inv0, o[dt][1]*inv0);
        float2 r1v = make_float2(o[dt][2]*inv1, o[dt][3]*inv1);
        *reinterpret_cast<float2*>(AO + ((size_t)(b*LL + row0))*DM + d) = r0v;
        *reinterpret_cast<float2*>(AO + ((size_t)(b*LL + row1))*DM + d) = r1v;
    }
}

// ---------------------------------------------------------------------------
extern "C" void kernel_launch(void* const* d_in, const int* in_sizes, int n_in,
                              void* d_out, int out_size)
{
    const float* queries  = (const float*)d_in[0];
    const float* keys     = (const float*)d_in[1];
    const float* values   = (const float*)d_in[2];
    const int*   key_mask = (const int*)  d_in[3];
    const float* Wq = (const float*)d_in[4];  const float* bq = (const float*)d_in[5];
    const float* Wk = (const float*)d_in[6];  const float* bk = (const float*)d_in[7];
    const float* Wv = (const float*)d_in[8];  const float* bv = (const float*)d_in[9];
    const float* Wo = (const float*)d_in[10]; const float* bo = (const float*)d_in[11];
    float* out = (float*)d_out;

    float *Qd, *Kd, *Vd, *AOd;
    cudaGetSymbolAddress((void**)&Qd,  g_Q);
    cudaGetSymbolAddress((void**)&Kd,  g_K);
    cudaGetSymbolAddress((void**)&Vd,  g_V);
    cudaGetSymbolAddress((void**)&AOd, g_AO);

    const dim3 ggrid(64, 4);
    gemm_bias_kernel<<<ggrid, 256>>>(queries, Wq, bq, Qd);
    gemm_bias_kernel<<<ggrid, 256>>>(keys,    Wk, bk, Kd);
    gemm_bias_kernel<<<ggrid, 256>>>(values,  Wv, bv, Vd);

    const dim3 agrid(LL/64, NH, BB);   // 32 x 8 x 2 = 512 CTAs
    attn_kernel<<<agrid, 128>>>(key_mask, AOd);

    gemm_bias_kernel<<<ggrid, 256>>>(AOd, Wo, bo, out);
}

// round 3
// speedup vs baseline: 3.0214x; 1.3725x over previous
#include <cuda_runtime.h>
#include <cuda_bf16.h>
#include <math_constants.h>

#define BB 2
#define LL 2048
#define DM 256
#define NH 8
#define DEPTH 32
#define KT 64
#define NEG_INF_F (-4294967296.0f)   /* float32(-2^32+1) */

// Scratch (allocation-free rule: __device__ globals)
__device__ float g_Q[BB*LL*DM];
__device__ float g_K[BB*LL*DM];
__device__ float g_V[BB*LL*DM];
__device__ float g_AO[BB*LL*DM];

// pack two floats to bf16x2 (lo -> low half), rn
__device__ __forceinline__ unsigned bpack(float lo, float hi) {
    unsigned d;
    asm("cvt.rn.bf16x2.f32 %0, %1, %2;" : "=r"(d) : "f"(hi), "f"(lo));
    return d;
}

// hi/lo bf16 split of two floats, packed (x0 -> low halves)
__device__ __forceinline__ void bsplit2(float x0, float x1, unsigned &h, unsigned &l) {
    float h0 = __bfloat162float(__float2bfloat16_rn(x0));
    float h1 = __bfloat162float(__float2bfloat16_rn(x1));
    h = bpack(h0, h1);
    l = bpack(x0 - h0, x1 - h1);
}

__device__ __forceinline__ void mma_bf16(float d[4], const unsigned a[4],
                                         const unsigned b[2], const float c[4]) {
    asm volatile("mma.sync.aligned.m16n8k16.row.col.f32.bf16.bf16.f32 "
                 "{%0,%1,%2,%3}, {%4,%5,%6,%7}, {%8,%9}, {%10,%11,%12,%13};"
                 : "=f"(d[0]), "=f"(d[1]), "=f"(d[2]), "=f"(d[3])
                 : "r"(a[0]), "r"(a[1]), "r"(a[2]), "r"(a[3]),
                   "r"(b[0]), "r"(b[1]),
                   "f"(c[0]), "f"(c[1]), "f"(c[2]), "f"(c[3]));
}

// ---------------------------------------------------------------------------
// GEMM: C[4096,256] = A[4096,256] @ W[256,256] + bias, bf16 split mma.
// CTA: 128 threads (4 warps), tile 64x64, k-tiles of 64.
// ---------------------------------------------------------------------------
__global__ __launch_bounds__(128) void gemm_bias_kernel(
    const float* __restrict__ A, const float* __restrict__ W,
    const float* __restrict__ bias, float* __restrict__ C)
{
    __shared__ unsigned Ahp[64][36], Alp[64][36];   // [m][kpair], pairs along k
    __shared__ unsigned Whp[32][72], Wlp[32][72];   // [kpair][n]

    const int t    = threadIdx.x;
    const int w    = t >> 5;
    const int lane = t & 31;
    const int g    = lane >> 2;
    const int c    = lane & 3;
    const int m0   = blockIdx.x * 64;
    const int n0   = blockIdx.y * 64;

    float acc[8][4];
    #pragma unroll
    for (int i = 0; i < 8; i++)
        #pragma unroll
        for (int j = 0; j < 4; j++) acc[i][j] = 0.f;

    for (int kt = 0; kt < 4; kt++) {
        const int k0 = kt * 64;
        __syncthreads();
        // stage A tile 64x64 -> hi/lo packed along k
        #pragma unroll
        for (int i = 0; i < 8; i++) {
            const int f  = t + i*128;        // 0..1023 float4s
            const int r  = f >> 4, d4 = f & 15;
            float4 a = reinterpret_cast<const float4*>(
                A + (size_t)(m0 + r)*256 + k0 + d4*4)[0];
            unsigned h0,l0,h1,l1;
            bsplit2(a.x, a.y, h0, l0);
            bsplit2(a.z, a.w, h1, l1);
            *reinterpret_cast<uint2*>(&Ahp[r][d4*2]) = make_uint2(h0, h1);
            *reinterpret_cast<uint2*>(&Alp[r][d4*2]) = make_uint2(l0, l1);
        }
        // stage W tile 64x64 -> hi/lo packed across k-row pairs
        #pragma unroll
        for (int i = 0; i < 4; i++) {
            const int f  = t + i*128;        // 0..511
            const int kp = f >> 4, n4 = f & 15;
            float4 wa = reinterpret_cast<const float4*>(
                W + (size_t)(k0 + 2*kp)*256 + n0 + n4*4)[0];
            float4 wb = reinterpret_cast<const float4*>(
                W + (size_t)(k0 + 2*kp + 1)*256 + n0 + n4*4)[0];
            uint4 hh, lll;
            bsplit2(wa.x, wb.x, hh.x, lll.x);
            bsplit2(wa.y, wb.y, hh.y, lll.y);
            bsplit2(wa.z, wb.z, hh.z, lll.z);
            bsplit2(wa.w, wb.w, hh.w, lll.w);
            *reinterpret_cast<uint4*>(&Whp[kp][n4*4]) = hh;
            *reinterpret_cast<uint4*>(&Wlp[kp][n4*4]) = lll;
        }
        __syncthreads();

        #pragma unroll
        for (int kc = 0; kc < 4; kc++) {
            const int r0 = w*16 + g, r1 = r0 + 8;
            unsigned ah[4] = { Ahp[r0][kc*8+c],   Ahp[r1][kc*8+c],
                               Ahp[r0][kc*8+c+4], Ahp[r1][kc*8+c+4] };
            unsigned al[4] = { Alp[r0][kc*8+c],   Alp[r1][kc*8+c],
                               Alp[r0][kc*8+c+4], Alp[r1][kc*8+c+4] };
            #pragma unroll
            for (int nt = 0; nt < 8; nt++) {
                unsigned bh[2] = { Whp[kc*8+c][nt*8+g], Whp[kc*8+c+4][nt*8+g] };
                unsigned bl[2] = { Wlp[kc*8+c][nt*8+g], Wlp[kc*8+c+4][nt*8+g] };
                mma_bf16(acc[nt], ah, bh, acc[nt]);
                mma_bf16(acc[nt], ah, bl, acc[nt]);
                mma_bf16(acc[nt], al, bh, acc[nt]);
            }
        }
    }

    // epilogue
    const int r0 = m0 + w*16 + g;
    #pragma unroll
    for (int nt = 0; nt < 8; nt++) {
        const int n = n0 + nt*8 + 2*c;
        const float b0 = bias[n], b1 = bias[n+1];
        *reinterpret_cast<float2*>(C + (size_t)r0*256 + n) =
            make_float2(acc[nt][0] + b0, acc[nt][1] + b1);
        *reinterpret_cast<float2*>(C + (size_t)(r0+8)*256 + n) =
            make_float2(acc[nt][2] + b0, acc[nt][3] + b1);
    }
}

// ---------------------------------------------------------------------------
// FA2-style attention with bf16 split mma (m16n8k16).
// CTA: 128 threads = 4 warps x 16 queries = 64 queries; key tiles of 64.
// QK and PV both 3-term hi/lo split -> ~fp32 accuracy.
// ---------------------------------------------------------------------------
__global__ __launch_bounds__(128) void attn_kernel(
    const int* __restrict__ key_mask, float* __restrict__ AO)
{
    __shared__ float    Qs[64][36];
    __shared__ unsigned Khp[64][20], Klp[64][20];  // [key][depth-pair]
    __shared__ unsigned Vhp[32][40], Vlp[32][40];  // [key-pair][depth]
    __shared__ float    biasS[64];

    const int b    = blockIdx.z;
    const int h    = blockIdx.y;
    const int t    = threadIdx.x;
    const int w    = t >> 5;
    const int lane = t & 31;
    const int g    = lane >> 2;
    const int c    = lane & 3;
    const int q0   = blockIdx.x * 64;

    const float scale = 0.17677669529663687f;  // 1/sqrt(32)

    // ---- stage Q tile (64x32) ----
    const float* Qg = g_Q + ((size_t)(b*LL + q0))*DM + h*DEPTH;
    #pragma unroll
    for (int i = 0; i < 4; i++) {
        const int f = t + i*128;
        const int r = f >> 3, d4 = f & 7;
        reinterpret_cast<float4*>(&Qs[r][0])[d4] =
            reinterpret_cast<const float4*>(Qg + (size_t)r*DM)[d4];
    }
    __syncthreads();

    // ---- Q A-fragments (scaled, hi/lo split, bf16x2 packed) ----
    unsigned qh[2][4], ql[2][4];
    {
        const int r0 = w*16 + g, r1 = r0 + 8;
        #pragma unroll
        for (int kc = 0; kc < 2; kc++) {
            const int c0 = kc*16 + 2*c;
            bsplit2(Qs[r0][c0]*scale,   Qs[r0][c0+1]*scale, qh[kc][0], ql[kc][0]);
            bsplit2(Qs[r1][c0]*scale,   Qs[r1][c0+1]*scale, qh[kc][1], ql[kc][1]);
            bsplit2(Qs[r0][c0+8]*scale, Qs[r0][c0+9]*scale, qh[kc][2], ql[kc][2]);
            bsplit2(Qs[r1][c0+8]*scale, Qs[r1][c0+9]*scale, qh[kc][3], ql[kc][3]);
        }
    }

    float o[4][4];
    #pragma unroll
    for (int i = 0; i < 4; i++)
        #pragma unroll
        for (int j = 0; j < 4; j++) o[i][j] = 0.f;
    float m0 = -CUDART_INF_F, m1 = -CUDART_INF_F;
    float l0 = 0.f, l1 = 0.f;

    for (int it = 0; it < LL/KT; it++) {
        const int k0 = it * KT;
        __syncthreads();

        // ---- stage K hi/lo (packed along depth) ----
        const float* Kg = g_K + ((size_t)(b*LL + k0))*DM + h*DEPTH;
        #pragma unroll
        for (int i = 0; i < 4; i++) {
            const int f = t + i*128;
            const int r = f >> 3, d4 = f & 7;
            float4 kv = reinterpret_cast<const float4*>(Kg + (size_t)r*DM)[d4];
            unsigned h0,lo0,h1,lo1;
            bsplit2(kv.x, kv.y, h0, lo0);
            bsplit2(kv.z, kv.w, h1, lo1);
            *reinterpret_cast<uint2*>(&Khp[r][d4*2]) = make_uint2(h0, h1);
            *reinterpret_cast<uint2*>(&Klp[r][d4*2]) = make_uint2(lo0, lo1);
        }
        // ---- stage V hi/lo (packed across key pairs) ----
        const float* Vg = g_V + ((size_t)(b*LL + k0))*DM + h*DEPTH;
        #pragma unroll
        for (int i = 0; i < 2; i++) {
            const int f  = t + i*128;       // 0..255
            const int kp = f >> 3, d4 = f & 7;
            float4 va = reinterpret_cast<const float4*>(Vg + (size_t)(2*kp)*DM)[d4];
            float4 vb = reinterpret_cast<const float4*>(Vg + (size_t)(2*kp+1)*DM)[d4];
            uint4 hh, lll;
            bsplit2(va.x, vb.x, hh.x, lll.x);
            bsplit2(va.y, vb.y, hh.y, lll.y);
            bsplit2(va.z, vb.z, hh.z, lll.z);
            bsplit2(va.w, vb.w, hh.w, lll.w);
            *reinterpret_cast<uint4*>(&Vhp[kp][d4*4]) = hh;
            *reinterpret_cast<uint4*>(&Vlp[kp][d4*4]) = lll;
        }
        if (t < 64)
            biasS[t] = key_mask[b*LL + k0 + t] ? 0.f : NEG_INF_F;
        __syncthreads();

        // ---- S = Q K^T + mask bias (16x64 per warp) ----
        float p[8][4];
        #pragma unroll
        for (int nt = 0; nt < 8; nt++) {
            const float bc0 = biasS[nt*8 + 2*c];
            const float bc1 = biasS[nt*8 + 2*c + 1];
            p[nt][0] = bc0; p[nt][1] = bc1; p[nt][2] = bc0; p[nt][3] = bc1;
            const int key = nt*8 + g;
            #pragma unroll
            for (int kc = 0; kc < 2; kc++) {
                unsigned bh[2] = { Khp[key][kc*8+c], Khp[key][kc*8+c+4] };
                unsigned bl[2] = { Klp[key][kc*8+c], Klp[key][kc*8+c+4] };
                mma_bf16(p[nt], qh[kc], bh, p[nt]);
                mma_bf16(p[nt], qh[kc], bl, p[nt]);
                mma_bf16(p[nt], ql[kc], bh, p[nt]);
            }
        }

        // ---- online softmax ----
        float rmax0 = -CUDART_INF_F, rmax1 = -CUDART_INF_F;
        #pragma unroll
        for (int nt = 0; nt < 8; nt++) {
            rmax0 = fmaxf(rmax0, fmaxf(p[nt][0], p[nt][1]));
            rmax1 = fmaxf(rmax1, fmaxf(p[nt][2], p[nt][3]));
        }
        rmax0 = fmaxf(rmax0, __shfl_xor_sync(0xffffffffu, rmax0, 1));
        rmax0 = fmaxf(rmax0, __shfl_xor_sync(0xffffffffu, rmax0, 2));
        rmax1 = fmaxf(rmax1, __shfl_xor_sync(0xffffffffu, rmax1, 1));
        rmax1 = fmaxf(rmax1, __shfl_xor_sync(0xffffffffu, rmax1, 2));

        const float mn0 = fmaxf(m0, rmax0);
        const float mn1 = fmaxf(m1, rmax1);
        const float al0 = __expf(m0 - mn0);
        const float al1 = __expf(m1 - mn1);
        m0 = mn0; m1 = mn1;
        l0 *= al0; l1 *= al1;
        #pragma unroll
        for (int dt = 0; dt < 4; dt++) {
            o[dt][0] *= al0; o[dt][1] *= al0;
            o[dt][2] *= al1; o[dt][3] *= al1;
        }

        float rs0 = 0.f, rs1 = 0.f;
        #pragma unroll
        for (int nt = 0; nt < 8; nt++) {
            p[nt][0] = __expf(p[nt][0] - mn0); rs0 += p[nt][0];
            p[nt][1] = __expf(p[nt][1] - mn0); rs0 += p[nt][1];
            p[nt][2] = __expf(p[nt][2] - mn1); rs1 += p[nt][2];
            p[nt][3] = __expf(p[nt][3] - mn1); rs1 += p[nt][3];
        }
        rs0 += __shfl_xor_sync(0xffffffffu, rs0, 1);
        rs0 += __shfl_xor_sync(0xffffffffu, rs0, 2);
        rs1 += __shfl_xor_sync(0xffffffffu, rs1, 1);
        rs1 += __shfl_xor_sync(0xffffffffu, rs1, 2);
        l0 += rs0; l1 += rs1;

        // ---- O += P V  (C-frag == A-frag layout for f16-family k16: no shuffles) ----
        #pragma unroll
        for (int kc = 0; kc < 4; kc++) {
            unsigned ph[4], pl[4];
            bsplit2(p[2*kc][0],   p[2*kc][1],   ph[0], pl[0]);
            bsplit2(p[2*kc][2],   p[2*kc][3],   ph[1], pl[1]);
            bsplit2(p[2*kc+1][0], p[2*kc+1][1], ph[2], pl[2]);
            bsplit2(p[2*kc+1][2], p[2*kc+1][3], ph[3], pl[3]);
            #pragma unroll
            for (int dt = 0; dt < 4; dt++) {
                unsigned vh[2] = { Vhp[kc*8+c][dt*8+g], Vhp[kc*8+c+4][dt*8+g] };
                unsigned vl[2] = { Vlp[kc*8+c][dt*8+g], Vlp[kc*8+c+4][dt*8+g] };
                mma_bf16(o[dt], ph, vh, o[dt]);
                mma_bf16(o[dt], ph, vl, o[dt]);
                mma_bf16(o[dt], pl, vh, o[dt]);
            }
        }
    }

    // ---- normalize + store ----
    const float inv0 = 1.f / l0;
    const float inv1 = 1.f / l1;
    const int row0 = q0 + w*16 + g;
    const int row1 = row0 + 8;
    #pragma unroll
    for (int dt = 0; dt < 4; dt++) {
        const int d = h*DEPTH + dt*8 + 2*c;
        *reinterpret_cast<float2*>(AO + ((size_t)(b*LL + row0))*DM + d) =
            make_float2(o[dt][0]*inv0, o[dt][1]*inv0);
        *reinterpret_cast<float2*>(AO + ((size_t)(b*LL + row1))*DM + d) =
            make_float2(o[dt][2]*inv1, o[dt][3]*inv1);
    }
}

// ---------------------------------------------------------------------------
extern "C" void kernel_launch(void* const* d_in, const int* in_sizes, int n_in,
                              void* d_out, int out_size)
{
    const float* queries  = (const float*)d_in[0];
    const float* keys     = (const float*)d_in[1];
    const float* values   = (const float*)d_in[2];
    const int*   key_mask = (const int*)  d_in[3];
    const float* Wq = (const float*)d_in[4];  const float* bq = (const float*)d_in[5];
    const float* Wk = (const float*)d_in[6];  const float* bk = (const float*)d_in[7];
    const float* Wv = (const float*)d_in[8];  const float* bv = (const float*)d_in[9];
    const float* Wo = (const float*)d_in[10]; const float* bo = (const float*)d_in[11];
    float* out = (float*)d_out;

    float *Qd, *Kd, *Vd, *AOd;
    cudaGetSymbolAddress((void**)&Qd,  g_Q);
    cudaGetSymbolAddress((void**)&Kd,  g_K);
    cudaGetSymbolAddress((void**)&Vd,  g_V);
    cudaGetSymbolAddress((void**)&AOd, g_AO);

    const dim3 ggrid(64, 4);
    gemm_bias_kernel<<<ggrid, 128>>>(queries, Wq, bq, Qd);
    gemm_bias_kernel<<<ggrid, 128>>>(keys,    Wk, bk, Kd);
    gemm_bias_kernel<<<ggrid, 128>>>(values,  Wv, bv, Vd);

    const dim3 agrid(LL/64, NH, BB);   // 32 x 8 x 2 = 512 CTAs
    attn_kernel<<<agrid, 128>>>(key_mask, AOd);

    gemm_bias_kernel<<<ggrid, 128>>>(AOd, Wo, bo, out);
}